// round 9
// baseline (speedup 1.0000x reference)
#include <cuda_runtime.h>
#include <cuda_bf16.h>

// Problem constants (fixed by the reference)
#define BB 2
#define CC 64
#define HH 512
#define WW 512
#define HW (HH * WW)          // 262144
#define NN 4096
#define KK 5
#define NPAIR (BB * NN)       // 8192
#define INV_MAXDIST (1.0f / 724.07733f)
#define FEAT_THRESH_NOMATCH 16.0f
#define FINAL_SCALE (1.0f / ((KK + 1.0f) * NN))   // 1/24576
// fixed-point: fp_i = total_i * FP_SCALE, FP_SCALE = FINAL_SCALE * 2^48 = 2^35/3
// finalize: out = (sum fp_i) * 2^-48  ->  sum total_i * FINAL_SCALE
#define FP_SCALE (34359738368.0f / 3.0f)          // 1.1453246123e10
#define FP_INV   (1.0 / 281474976710656.0)        // 2^-48

// Scratch (allocation-free rule: __device__ globals)
__device__ float g_fr[NPAIR * CC];      // compacted ref features   [b][i][c]
__device__ float g_fo[NPAIR * CC];      // compacted other features [b][i][c]
__device__ int   g_order[4][NN];        // per set: packed (lin<<12 | point id)
__device__ unsigned long long g_isum;   // fixed-point loss accumulator
__device__ unsigned int       g_ticket; // completion counter (warps)

// ---------------------------------------------------------------------------
// Kernel S: counting sort of the 4 point sets (ref b0/b1, oth b0/b1) by y-row.
// One block of 1024 threads per set. Also resets the accumulators (block 0).
// Within-row order is arbitrary but downstream results are written per-id and
// summed in integer fixed point -> output is bit-deterministic.
// ---------------------------------------------------------------------------
__global__ void __launch_bounds__(1024) sort_kernel(
        const int* __restrict__ inds_ref,
        const int* __restrict__ inds_other) {
    if (blockIdx.x == 0 && threadIdx.x == 0) {
        g_isum = 0ULL;
        g_ticket = 0u;
    }
    int s = blockIdx.x;           // 0,1 = ref b0,b1 ; 2,3 = oth b0,b1
    int t = s >> 1, b = s & 1;
    const int* inds = t ? inds_other : inds_ref;

    __shared__ int lin_s[NN];         // 16 KB
    __shared__ int hist[512];
    __shared__ int sc[2][512];
    __shared__ int offs[512];

    for (int k = threadIdx.x; k < 512; k += 1024) hist[k] = 0;
    __syncthreads();

    for (int i = threadIdx.x; i < NN; i += 1024) {
        int x = inds[b * 2 * NN + i];
        int y = inds[b * 2 * NN + NN + i];
        int lin = (y << 9) | x;       // 512*y + x
        lin_s[i] = lin;
        atomicAdd(&hist[y], 1);
    }
    __syncthreads();

    // inclusive scan of hist[512]
    if (threadIdx.x < 512) sc[0][threadIdx.x] = hist[threadIdx.x];
    __syncthreads();
    int p = 0;
#pragma unroll
    for (int d = 1; d < 512; d <<= 1) {
        if (threadIdx.x < 512) {
            int v = sc[p][threadIdx.x];
            if ((int)threadIdx.x >= d) v += sc[p][threadIdx.x - d];
            sc[p ^ 1][threadIdx.x] = v;
        }
        __syncthreads();
        p ^= 1;
    }
    if (threadIdx.x < 512)
        offs[threadIdx.x] = sc[p][threadIdx.x] - hist[threadIdx.x];  // exclusive
    __syncthreads();

    for (int i = threadIdx.x; i < NN; i += 1024) {
        int lin = lin_s[i];
        int pos = atomicAdd(&offs[lin >> 9], 1);
        g_order[s][pos] = (lin << 12) | i;
    }
}

// ---------------------------------------------------------------------------
// Kernel A: sorted gather. warp <-> (set, channel-group, chunk of 32 sorted
// points). Per load-slot a warp reads 32 ascending addresses in one plane ->
// DRAM row-buffer hits + coalescer line merges.
// ---------------------------------------------------------------------------
__global__ void __launch_bounds__(256) gather_sorted_kernel(
        const float* __restrict__ ref,
        const float* __restrict__ oth) {
    int gw   = (blockIdx.x * blockDim.x + threadIdx.x) >> 5;  // 0..8191
    int lane = threadIdx.x & 31;
    int s    = gw >> 11;          // set (4)
    int qg   = (gw >> 7) & 15;    // channel group (16)
    int chnk = gw & 127;          // sorted chunk (128)
    int t = s >> 1, b = s & 1;

    int packed = g_order[s][chnk * 32 + lane];
    int lin = packed >> 12;
    int id  = packed & 4095;

    const float* src = (t ? oth : ref) + (size_t)(b * CC + 4 * qg) * HW + lin;
    float v0 = __ldg(src + 0 * HW);
    float v1 = __ldg(src + 1 * HW);
    float v2 = __ldg(src + 2 * HW);
    float v3 = __ldg(src + 3 * HW);

    float* dst = (t ? g_fo : g_fr) + (size_t)((b << 12) | id) * CC + 4 * qg;
    *reinterpret_cast<float4*>(dst) = make_float4(v0, v1, v2, v3);
}

// ---------------------------------------------------------------------------
// Kernel B: one warp per match pair; feature reads coalesced from the compact
// arrays (L2-resident). Each warp atomically adds its fixed-point partial;
// the last warp to finish writes the final float output. Integer atomics are
// associative -> bit-deterministic across graph replays.
// ---------------------------------------------------------------------------
__global__ void __launch_bounds__(256) match_kernel(
        const float* __restrict__ weights,
        const int* __restrict__ inds_ref,
        const int* __restrict__ rand_inds,
        float* __restrict__ out) {
    int gwarp = (blockIdx.x * blockDim.x + threadIdx.x) >> 5;
    int lane  = threadIdx.x & 31;
    int b = gwarp >> 12;
    int i = gwarp & (NN - 1);

    const float2* frp = reinterpret_cast<const float2*>(g_fr + (size_t)gwarp * CC);
    const float2* fop = reinterpret_cast<const float2*>(g_fo + (size_t)gwarp * CC);
    float2 fr = frp[lane];
    float2 fo = fop[lane];
    float d0 = fr.x - fo.x, d1 = fr.y - fo.y;
    float sm = d0 * d0 + d1 * d1;

    int   jarr[KK];
    float sk[KK];
    const int* ri = rand_inds + (size_t)gwarp * KK;
#pragma unroll
    for (int k = 0; k < KK; k++) {
        int j = __ldg(ri + k);             // uniform across warp (broadcast)
        jarr[k] = j;
        const float2* fo_j =
            reinterpret_cast<const float2*>(g_fo + (size_t)(b * NN + j) * CC);
        float2 fj = fo_j[lane];
        float e0 = fr.x - fj.x, e1 = fr.y - fj.y;
        sk[k] = e0 * e0 + e1 * e1;
    }

#pragma unroll
    for (int off = 16; off > 0; off >>= 1) {
        sm += __shfl_down_sync(0xFFFFFFFFu, sm, off);
#pragma unroll
        for (int k = 0; k < KK; k++)
            sk[k] += __shfl_down_sync(0xFFFFFFFFu, sk[k], off);
    }

    if (lane == 0) {
        int xr = inds_ref[b * 2 * NN + i];
        int yr = inds_ref[b * 2 * NN + NN + i];
        float total = weights[b * NN + i] * fmaxf(sm, 0.0f);
#pragma unroll
        for (int k = 0; k < KK; k++) {
            int j  = jarr[k];
            float xj = (float)inds_ref[b * 2 * NN + j];
            float yj = (float)inds_ref[b * 2 * NN + NN + j];
            float dx = (float)xr - xj;
            float dy = (float)yr - yj;
            float dist = sqrtf(dx * dx + dy * dy);
            total += (-dist * INV_MAXDIST) * fminf(sk[k], FEAT_THRESH_NOMATCH);
        }
        long long fp = llrintf(total * FP_SCALE);
        atomicAdd(&g_isum, (unsigned long long)fp);
        __threadfence();
        unsigned int t = atomicAdd(&g_ticket, 1u);
        if (t == NPAIR - 1) {
            // all other warps' adds are fence-ordered before their tickets
            long long s = (long long)g_isum;
            out[0] = (float)((double)s * FP_INV);
        }
    }
}

extern "C" void kernel_launch(void* const* d_in, const int* in_sizes, int n_in,
                              void* d_out, int out_size) {
    const float* inputs_ref   = (const float*)d_in[0];
    const float* inputs_other = (const float*)d_in[1];
    const float* weights      = (const float*)d_in[2];
    const int*   inds_ref     = (const int*)d_in[3];
    const int*   inds_other   = (const int*)d_in[4];
    const int*   rand_inds    = (const int*)d_in[5];
    float* out = (float*)d_out;

    sort_kernel<<<4, 1024>>>(inds_ref, inds_other);
    gather_sorted_kernel<<<1024, 256>>>(inputs_ref, inputs_other);
    match_kernel<<<1024, 256>>>(weights, inds_ref, rand_inds, out);
}

// round 10
// speedup vs baseline: 1.2763x; 1.2763x over previous
#include <cuda_runtime.h>
#include <cuda_bf16.h>

// Problem constants (fixed by the reference)
#define BB 2
#define CC 64
#define HH 512
#define WW 512
#define HW (HH * WW)          // 262144
#define NN 4096
#define KK 5
#define NPAIR (BB * NN)       // 8192
#define INV_MAXDIST (1.0f / 724.07733f)
#define FEAT_THRESH_NOMATCH 16.0f
// fixed-point: fp_i = total_i * FP_SCALE, FP_SCALE = (1/24576) * 2^48 = 2^35/3
// finalize: out = (sum fp_i) * 2^-48
#define FP_SCALE (34359738368.0f / 3.0f)          // 1.1453246123e10
#define FP_INV   (1.0 / 281474976710656.0)        // 2^-48
#define MATCH_BLOCKS 1024

// Scratch (allocation-free rule: __device__ globals)
__device__ float g_fr[NPAIR * CC];      // compacted ref features   [b][i][c]
__device__ float g_fo[NPAIR * CC];      // compacted other features [b][i][c]
__device__ int   g_order[4][NN];        // per set: packed (lin<<12 | point id)
__device__ unsigned long long g_isum;   // fixed-point loss accumulator
__device__ unsigned int       g_ticket; // completion counter (blocks)

// ---------------------------------------------------------------------------
// Kernel S: counting sort of the 4 point sets (ref b0/b1, oth b0/b1) by y-row.
// One block of 1024 threads per set. Shuffle-based two-level scan (4 syncs).
// Block 0 also resets the global accumulators for graph-replay determinism.
// ---------------------------------------------------------------------------
__global__ void __launch_bounds__(1024) sort_kernel(
        const int* __restrict__ inds_ref,
        const int* __restrict__ inds_other) {
    if (blockIdx.x == 0 && threadIdx.x == 0) {
        g_isum = 0ULL;
        g_ticket = 0u;
    }
    int s = blockIdx.x;           // 0,1 = ref b0,b1 ; 2,3 = oth b0,b1
    int t = s >> 1, b = s & 1;
    const int* inds = t ? inds_other : inds_ref;

    __shared__ int lin_s[NN];         // 16 KB
    __shared__ int hist[512];
    __shared__ int wsum[16];
    __shared__ int offs[512];

    int tid  = threadIdx.x;
    int lane = tid & 31;
    int w    = tid >> 5;

    if (tid < 512) hist[tid] = 0;
    __syncthreads();

    for (int i = tid; i < NN; i += 1024) {
        int x = inds[b * 2 * NN + i];
        int y = inds[b * 2 * NN + NN + i];
        int lin = (y << 9) | x;       // 512*y + x
        lin_s[i] = lin;
        atomicAdd(&hist[y], 1);
    }
    __syncthreads();

    // two-level scan: 16 warps each scan 32 buckets via shfl
    int v = 0;
    if (tid < 512) {
        v = hist[tid];
#pragma unroll
        for (int d = 1; d < 32; d <<= 1) {
            int u = __shfl_up_sync(0xFFFFFFFFu, v, d);
            if (lane >= d) v += u;
        }
        if (lane == 31) wsum[w] = v;   // inclusive warp totals (w = 0..15)
    }
    __syncthreads();
    if (tid < 32) {
        int u = (tid < 16) ? wsum[tid] : 0;
#pragma unroll
        for (int d = 1; d < 16; d <<= 1) {
            int x2 = __shfl_up_sync(0xFFFFFFFFu, u, d);
            if (lane >= d) u += x2;
        }
        if (tid < 16) wsum[tid] = u;   // inclusive across warps
    }
    __syncthreads();
    if (tid < 512) {
        int base = (w > 0) ? wsum[w - 1] : 0;
        offs[tid] = base + v - hist[tid];   // exclusive prefix
    }
    __syncthreads();

    for (int i = tid; i < NN; i += 1024) {
        int lin = lin_s[i];
        int pos = atomicAdd(&offs[lin >> 9], 1);
        g_order[s][pos] = (lin << 12) | i;
    }
}

// ---------------------------------------------------------------------------
// Kernel A: sorted gather. warp <-> (set, channel-group, chunk of 32 sorted
// points). Per load-slot a warp reads 32 ascending addresses in one plane ->
// DRAM row-buffer hits + coalescer line merges.
// ---------------------------------------------------------------------------
__global__ void __launch_bounds__(256) gather_sorted_kernel(
        const float* __restrict__ ref,
        const float* __restrict__ oth) {
    int gw   = (blockIdx.x * blockDim.x + threadIdx.x) >> 5;  // 0..8191
    int lane = threadIdx.x & 31;
    int s    = gw >> 11;          // set (4)
    int qg   = (gw >> 7) & 15;    // channel group (16)
    int chnk = gw & 127;          // sorted chunk (128)
    int t = s >> 1, b = s & 1;

    int packed = g_order[s][chnk * 32 + lane];
    int lin = packed >> 12;
    int id  = packed & 4095;

    const float* src = (t ? oth : ref) + (size_t)(b * CC + 4 * qg) * HW + lin;
    float v0 = __ldg(src + 0 * HW);
    float v1 = __ldg(src + 1 * HW);
    float v2 = __ldg(src + 2 * HW);
    float v3 = __ldg(src + 3 * HW);

    float* dst = (t ? g_fo : g_fr) + (size_t)((b << 12) | id) * CC + 4 * qg;
    *reinterpret_cast<float4*>(dst) = make_float4(v0, v1, v2, v3);
}

// ---------------------------------------------------------------------------
// Kernel B: one warp per match pair; feature reads coalesced from the compact
// arrays (L2-resident). Per-block smem reduction of the 8 warp partials, then
// ONE integer atomic + ticket per block (2048 atomics total, ~1us). Integer
// adds are associative -> bit-deterministic output across graph replays.
// ---------------------------------------------------------------------------
__global__ void __launch_bounds__(256) match_kernel(
        const float* __restrict__ weights,
        const int* __restrict__ inds_ref,
        const int* __restrict__ rand_inds,
        float* __restrict__ out) {
    __shared__ long long s_fp[8];
    int gwarp = (blockIdx.x * blockDim.x + threadIdx.x) >> 5;
    int lane  = threadIdx.x & 31;
    int wib   = (threadIdx.x >> 5);    // warp in block (0..7)
    int b = gwarp >> 12;
    int i = gwarp & (NN - 1);

    const float2* frp = reinterpret_cast<const float2*>(g_fr + (size_t)gwarp * CC);
    const float2* fop = reinterpret_cast<const float2*>(g_fo + (size_t)gwarp * CC);
    float2 fr = frp[lane];
    float2 fo = fop[lane];
    float d0 = fr.x - fo.x, d1 = fr.y - fo.y;
    float sm = d0 * d0 + d1 * d1;

    int   jarr[KK];
    float sk[KK];
    const int* ri = rand_inds + (size_t)gwarp * KK;
#pragma unroll
    for (int k = 0; k < KK; k++) {
        int j = __ldg(ri + k);             // uniform across warp (broadcast)
        jarr[k] = j;
        const float2* fo_j =
            reinterpret_cast<const float2*>(g_fo + (size_t)(b * NN + j) * CC);
        float2 fj = fo_j[lane];
        float e0 = fr.x - fj.x, e1 = fr.y - fj.y;
        sk[k] = e0 * e0 + e1 * e1;
    }

#pragma unroll
    for (int off = 16; off > 0; off >>= 1) {
        sm += __shfl_down_sync(0xFFFFFFFFu, sm, off);
#pragma unroll
        for (int k = 0; k < KK; k++)
            sk[k] += __shfl_down_sync(0xFFFFFFFFu, sk[k], off);
    }

    if (lane == 0) {
        int xr = inds_ref[b * 2 * NN + i];
        int yr = inds_ref[b * 2 * NN + NN + i];
        float total = weights[b * NN + i] * fmaxf(sm, 0.0f);
#pragma unroll
        for (int k = 0; k < KK; k++) {
            int j  = jarr[k];
            float xj = (float)inds_ref[b * 2 * NN + j];
            float yj = (float)inds_ref[b * 2 * NN + NN + j];
            float dx = (float)xr - xj;
            float dy = (float)yr - yj;
            float dist = sqrtf(dx * dx + dy * dy);
            total += (-dist * INV_MAXDIST) * fminf(sk[k], FEAT_THRESH_NOMATCH);
        }
        s_fp[wib] = llrintf(total * FP_SCALE);
    }
    __syncthreads();

    if (threadIdx.x == 0) {
        long long blk = 0;
#pragma unroll
        for (int k = 0; k < 8; k++) blk += s_fp[k];
        atomicAdd(&g_isum, (unsigned long long)blk);
        __threadfence();
        unsigned int t = atomicAdd(&g_ticket, 1u);
        if (t == MATCH_BLOCKS - 1) {
            // all other blocks' adds are fence-ordered before their tickets
            long long s = (long long)g_isum;
            out[0] = (float)((double)s * FP_INV);
        }
    }
}

extern "C" void kernel_launch(void* const* d_in, const int* in_sizes, int n_in,
                              void* d_out, int out_size) {
    const float* inputs_ref   = (const float*)d_in[0];
    const float* inputs_other = (const float*)d_in[1];
    const float* weights      = (const float*)d_in[2];
    const int*   inds_ref     = (const int*)d_in[3];
    const int*   inds_other   = (const int*)d_in[4];
    const int*   rand_inds    = (const int*)d_in[5];
    float* out = (float*)d_out;

    sort_kernel<<<4, 1024>>>(inds_ref, inds_other);
    gather_sorted_kernel<<<1024, 256>>>(inputs_ref, inputs_other);
    match_kernel<<<MATCH_BLOCKS, 256>>>(weights, inds_ref, rand_inds, out);
}